// round 3
// baseline (speedup 1.0000x reference)
#include <cuda_runtime.h>
#include <math.h>

// Problem constants
#define BB 4
#define LL 2048
#define DD 512
#define HH 8
#define DKK 64
#define UU 24            // u_part == n_top == min(3*ceil(ln(2048)), 2048) = 24
#define BH (BB*HH)

// ---------------- scratch (device globals; no allocation allowed) ----------
__device__ float g_q[BB*HH*LL*DKK];     // (B,H,L,DK)
__device__ float g_k[BB*HH*LL*DKK];
__device__ float g_v[BB*HH*LL*DKK];
__device__ float g_m[BB*HH*LL];         // sparsity measure
__device__ int   g_top[BB*HH*UU];       // top-k indices per (b,h)
__device__ float g_att[BB*HH*UU*DKK];   // attention outputs for top rows
__device__ float g_ctx[BB*LL*DD];       // context in (b, l, h*DK+dk) layout

// ---------------------------------------------------------------------------
// SGEMM: C[M=8192, N=512] = A[M,512] @ W[512,512] + bias
// MODE 0: A is ignored; reads g_ctx (device symbol) and writes row-major outp
// MODE 1/2/3: reads A param; scatters into g_q / g_k / g_v with (B,H,L,DK)
// 128x128 block tile, BK=8, 256 threads, 8x8 per-thread micro tile.
// NOTE: device globals must only be referenced from device code.
// ---------------------------------------------------------------------------
template<int MODE>
__global__ __launch_bounds__(256) void sgemm_kernel(const float* __restrict__ Ain,
                                                    const float* __restrict__ W,
                                                    const float* __restrict__ bias,
                                                    float* __restrict__ outp)
{
    const float* A = (MODE == 0) ? (const float*)g_ctx : Ain;

    __shared__ float As[8][128];
    __shared__ float Bs[8][128];
    const int tid = threadIdx.x;
    const int m0 = blockIdx.y * 128;
    const int n0 = blockIdx.x * 128;

    const int aRow = tid >> 1;          // 0..127
    const int aCol = (tid & 1) * 4;     // 0 or 4
    const int bRow = tid >> 5;          // 0..7
    const int bCol = (tid & 31) * 4;    // 0..124

    const int ty = tid >> 4;            // 0..15
    const int tx = tid & 15;            // 0..15

    float acc[8][8];
#pragma unroll
    for (int i = 0; i < 8; i++)
#pragma unroll
        for (int j = 0; j < 8; j++) acc[i][j] = 0.f;

    for (int k0 = 0; k0 < 512; k0 += 8) {
        float4 a4 = *(const float4*)(A + (size_t)(m0 + aRow) * 512 + k0 + aCol);
        As[aCol + 0][aRow] = a4.x;
        As[aCol + 1][aRow] = a4.y;
        As[aCol + 2][aRow] = a4.z;
        As[aCol + 3][aRow] = a4.w;
        float4 b4 = *(const float4*)(W + (size_t)(k0 + bRow) * 512 + n0 + bCol);
        *(float4*)(&Bs[bRow][bCol]) = b4;
        __syncthreads();
#pragma unroll
        for (int kk = 0; kk < 8; kk++) {
            float ra[8], rb[8];
#pragma unroll
            for (int i = 0; i < 8; i++) ra[i] = As[kk][ty * 8 + i];
#pragma unroll
            for (int j = 0; j < 8; j++) rb[j] = Bs[kk][tx * 8 + j];
#pragma unroll
            for (int i = 0; i < 8; i++)
#pragma unroll
                for (int j = 0; j < 8; j++)
                    acc[i][j] += ra[i] * rb[j];
        }
        __syncthreads();
    }

#pragma unroll
    for (int i = 0; i < 8; i++) {
        const int m = m0 + ty * 8 + i;
#pragma unroll
        for (int j = 0; j < 8; j++) {
            const int n = n0 + tx * 8 + j;
            const float val = acc[i][j] + bias[n];
            if (MODE == 0) {
                outp[(size_t)m * 512 + n] = val;
            } else {
                const int b = m >> 11;      // m / L
                const int l = m & 2047;     // m % L
                const int h = n >> 6;       // n / DK
                const int dk = n & 63;      // n % DK
                float* dst = (MODE == 1) ? g_q : (MODE == 2) ? g_k : g_v;
                dst[(((size_t)(b * HH + h) * LL + l) * DKK) + dk] = val;
            }
        }
    }
}

// ---------------------------------------------------------------------------
// Sparsity measure: m[b,h,l] = max_s(q·k_sample) - sum_s(q·k_sample)/L
// One warp per (b,h,l); lanes split the 64-dim dot.
// ---------------------------------------------------------------------------
__global__ __launch_bounds__(256) void probe_kernel(const int* __restrict__ idx)
{
    const int w = (blockIdx.x * blockDim.x + threadIdx.x) >> 5;
    const int lane = threadIdx.x & 31;
    if (w >= BB * HH * LL) return;
    const int l = w & (LL - 1);
    const int bh = w >> 11;

    const float* qrow = g_q + (size_t)(bh * LL + l) * DKK;
    const float q0 = qrow[lane];
    const float q1 = qrow[lane + 32];
    const float* kbase = g_k + (size_t)bh * LL * DKK;
    const int* ip = idx + l * UU;

    float mx = -INFINITY, sm = 0.f;
#pragma unroll 4
    for (int s = 0; s < UU; s++) {
        const int j = ip[s];
        const float* kr = kbase + (size_t)j * DKK;
        float p = q0 * kr[lane] + q1 * kr[lane + 32];
#pragma unroll
        for (int o = 16; o > 0; o >>= 1) p += __shfl_xor_sync(0xffffffffu, p, o);
        mx = fmaxf(mx, p);
        sm += p;
    }
    if (lane == 0) g_m[w] = mx - sm * (1.0f / LL);
}

// ---------------------------------------------------------------------------
// Top-24 per (b,h): iterative block argmax over 2048 values (tie -> smaller idx)
// ---------------------------------------------------------------------------
__global__ __launch_bounds__(256) void topk_kernel()
{
    __shared__ float vals[LL];
    __shared__ float rv[256];
    __shared__ int   ri[256];
    const int bh = blockIdx.x;
    const int t = threadIdx.x;

    for (int i = t; i < LL; i += 256) vals[i] = g_m[(size_t)bh * LL + i];
    __syncthreads();

    for (int iter = 0; iter < UU; iter++) {
        float bestv = -INFINITY; int besti = 0;
        for (int i = t; i < LL; i += 256) {
            const float v = vals[i];
            if (v > bestv) { bestv = v; besti = i; }
        }
        rv[t] = bestv; ri[t] = besti;
        __syncthreads();
        for (int s = 128; s > 0; s >>= 1) {
            if (t < s) {
                if (rv[t + s] > rv[t] ||
                    (rv[t + s] == rv[t] && ri[t + s] < ri[t])) {
                    rv[t] = rv[t + s]; ri[t] = ri[t + s];
                }
            }
            __syncthreads();
        }
        if (t == 0) {
            g_top[bh * UU + iter] = ri[0];
            vals[ri[0]] = -INFINITY;
        }
        __syncthreads();
    }
}

// ---------------------------------------------------------------------------
// Sparse attention for selected rows: one block per (b,h,u)
// scores over all 2048 keys, causal mask (j > pos), softmax, weighted V sum.
// ---------------------------------------------------------------------------
__global__ __launch_bounds__(256) void attn_kernel()
{
    __shared__ float sc[LL];
    __shared__ float qs[DKK];
    __shared__ float red[256];

    const int blk = blockIdx.x;          // bh*U + u
    const int bh = blk / UU;
    const int t = threadIdx.x;
    const int pos = g_top[blk];

    const float* kb = g_k + (size_t)bh * LL * DKK;
    const float* vb = g_v + (size_t)bh * LL * DKK;

    if (t < DKK) qs[t] = g_q[((size_t)bh * LL + pos) * DKK + t];
    __syncthreads();

    const float scale = rsqrtf((float)DD);   // 1/sqrt(d_out) = 1/sqrt(512)

    float lmax = -INFINITY;
    for (int j = t; j < LL; j += 256) {
        const float* kr = kb + (size_t)j * DKK;
        float dot = 0.f;
#pragma unroll
        for (int d = 0; d < DKK; d++) dot += qs[d] * kr[d];
        const float s = (j > pos) ? -INFINITY : dot * scale;
        sc[j] = s;
        lmax = fmaxf(lmax, s);
    }
    red[t] = lmax; __syncthreads();
    for (int s = 128; s > 0; s >>= 1) {
        if (t < s) red[t] = fmaxf(red[t], red[t + s]);
        __syncthreads();
    }
    const float mx = red[0];
    __syncthreads();

    float lsum = 0.f;
    for (int j = t; j < LL; j += 256) {
        const float p = expf(sc[j] - mx);
        sc[j] = p;
        lsum += p;
    }
    red[t] = lsum; __syncthreads();
    for (int s = 128; s > 0; s >>= 1) {
        if (t < s) red[t] += red[t + s];
        __syncthreads();
    }
    const float inv = 1.0f / red[0];
    __syncthreads();

    // phase 2: out[d] = sum_j p_j * v[j,d] / Z ; 4 key-groups x 64 dims
    const int d = t & 63;
    const int g = t >> 6;
    float acc = 0.f;
    const int j0 = g * (LL / 4), j1 = j0 + (LL / 4);
    for (int j = j0; j < j1; j++) acc += sc[j] * vb[(size_t)j * DKK + d];
    red[t] = acc; __syncthreads();
    if (t < DKK) {
        const float o = (red[t] + red[t + 64] + red[t + 128] + red[t + 192]) * inv;
        g_att[(size_t)blk * DKK + t] = o;
    }
}

// ---------------------------------------------------------------------------
// cumsum of V over sequence, written into (b, l, h*DK+d) layout of g_ctx.
// One block per (b,h), 4 chunk-groups x 64 dims.
// ---------------------------------------------------------------------------
__global__ __launch_bounds__(256) void cumsum_kernel()
{
    __shared__ float part[4][DKK];
    const int bh = blockIdx.x;
    const int b = bh >> 3, h = bh & 7;
    const int t = threadIdx.x;
    const int d = t & 63, c = t >> 6;
    const float* vb = g_v + (size_t)bh * LL * DKK;

    const int l0 = c * (LL / 4), l1 = l0 + (LL / 4);
    float s = 0.f;
    for (int l = l0; l < l1; l++) s += vb[(size_t)l * DKK + d];
    part[c][d] = s;
    __syncthreads();

    float off = 0.f;
    for (int cc = 0; cc < c; cc++) off += part[cc][d];

    float acc = off;
    float* cb = g_ctx + (size_t)b * LL * DD + h * DKK;
    for (int l = l0; l < l1; l++) {
        acc += vb[(size_t)l * DKK + d];
        cb[(size_t)l * DD + d] = acc;
    }
}

// ---------------------------------------------------------------------------
// Scatter attention outputs over the cumsum context at top-k rows.
// ---------------------------------------------------------------------------
__global__ void scatter_kernel()
{
    const int i = blockIdx.x * blockDim.x + threadIdx.x;
    if (i >= BB * HH * UU * DKK) return;
    const int d = i & 63;
    const int r = i >> 6;            // bh*U + u
    const int bh = r / UU;
    const int b = bh >> 3, h = bh & 7;
    const int pos = g_top[r];
    g_ctx[((size_t)b * LL + pos) * DD + h * DKK + d] = g_att[i];
}

// ---------------------------------------------------------------------------
extern "C" void kernel_launch(void* const* d_in, const int* in_sizes, int n_in,
                              void* d_out, int out_size)
{
    const float* queries = (const float*)d_in[0];
    const float* keys    = (const float*)d_in[1];
    const float* values  = (const float*)d_in[2];
    const int*   index_sample = (const int*)d_in[3];
    const float* Wq = (const float*)d_in[4];
    const float* bq = (const float*)d_in[5];
    const float* Wk = (const float*)d_in[6];
    const float* bk = (const float*)d_in[7];
    const float* Wv = (const float*)d_in[8];
    const float* bv = (const float*)d_in[9];
    const float* Wo = (const float*)d_in[10];
    const float* bo = (const float*)d_in[11];
    float* out = (float*)d_out;

    dim3 ggrid(DD / 128, (BB * LL) / 128);   // (4, 64)
    sgemm_kernel<1><<<ggrid, 256>>>(queries, Wq, bq, nullptr);
    sgemm_kernel<2><<<ggrid, 256>>>(keys,    Wk, bk, nullptr);
    sgemm_kernel<3><<<ggrid, 256>>>(values,  Wv, bv, nullptr);

    probe_kernel<<<(BB * HH * LL * 32) / 256, 256>>>(index_sample);
    topk_kernel<<<BH, 256>>>();
    attn_kernel<<<BH * UU, 256>>>();
    cumsum_kernel<<<BH, 256>>>();
    scatter_kernel<<<(BB * HH * UU * DKK + 255) / 256, 256>>>();

    // MODE 0 reads g_ctx from device code (device symbols are NOT valid host
    // pointers — passing g_ctx as an arg from host was the R2 bug).
    sgemm_kernel<0><<<ggrid, 256>>>(nullptr, Wo, bo, out);
}

// round 5
// speedup vs baseline: 1.3196x; 1.3196x over previous
#include <cuda_runtime.h>
#include <cuda_bf16.h>
#include <math.h>
#include <stdint.h>

// Problem constants
#define BB 4
#define LL 2048
#define DD 512
#define HH 8
#define DKK 64
#define UU 24
#define BH (BB*HH)
#define MTOT (BB*LL)     // 8192 rows per GEMM

// ---------------- scratch (device globals; no allocation allowed) ----------
__device__ float g_q[BB*HH*LL*DKK];     // (B,H,L,DK)
__device__ float g_k[BB*HH*LL*DKK];
__device__ float g_v[BB*HH*LL*DKK];
__device__ float g_m[BB*HH*LL];
__device__ int   g_top[BB*HH*UU];
__device__ float g_att[BB*HH*UU*DKK];
__device__ float g_ctx[BB*LL*DD];       // (b, l, h*DK+dk)

// bf16 hi/lo split operands for tensor-core GEMMs
__device__ __nv_bfloat16 g_ah[3][MTOT*DD];   // A hi (slots: q,k,v; slot0 reused for ctx)
__device__ __nv_bfloat16 g_al[3][MTOT*DD];   // A lo
__device__ __nv_bfloat16 g_wh[4][DD*DD];     // W^T hi: [n][k]  (Wq,Wk,Wv,Wo)
__device__ __nv_bfloat16 g_wl[4][DD*DD];     // W^T lo

// =========================== helpers =======================================
__device__ __forceinline__ uint32_t smem_u32(const void* p) {
    uint32_t a;
    asm("{ .reg .u64 t; cvta.to.shared.u64 t, %1; cvt.u32.u64 %0, t; }"
        : "=r"(a) : "l"(p));
    return a;
}
__device__ __forceinline__ void cpasync16(uint32_t saddr, const void* gptr) {
    asm volatile("cp.async.cg.shared.global [%0], [%1], 16;"
                 :: "r"(saddr), "l"(__cvta_generic_to_global(gptr)) : "memory");
}
__device__ __forceinline__ void cp_commit() {
    asm volatile("cp.async.commit_group;" ::: "memory");
}
template<int N>
__device__ __forceinline__ void cp_wait() {
    asm volatile("cp.async.wait_group %0;" :: "n"(N) : "memory");
}
__device__ __forceinline__ void mma_bf16(float& c0, float& c1, float& c2, float& c3,
                                         uint32_t a0, uint32_t a1, uint32_t a2, uint32_t a3,
                                         uint32_t b0, uint32_t b1) {
    asm volatile("mma.sync.aligned.m16n8k16.row.col.f32.bf16.bf16.f32 "
                 "{%0,%1,%2,%3}, {%4,%5,%6,%7}, {%8,%9}, {%0,%1,%2,%3};"
                 : "+f"(c0), "+f"(c1), "+f"(c2), "+f"(c3)
                 : "r"(a0), "r"(a1), "r"(a2), "r"(a3), "r"(b0), "r"(b1));
}
__device__ __forceinline__ void split2(float x, __nv_bfloat16& h, __nv_bfloat16& l) {
    h = __float2bfloat16_rn(x);
    l = __float2bfloat16_rn(x - __bfloat162float(h));
}

// =========================== conversion kernels ============================
// fp32 -> bf16 hi/lo (vectorized). src==nullptr means read g_ctx.
__global__ __launch_bounds__(256) void convert_split_kernel(const float* __restrict__ src,
                                                            int slot)
{
    const float* s = src ? src : (const float*)g_ctx;
    const int i = blockIdx.x * blockDim.x + threadIdx.x;   // over float4s
    if (i >= MTOT * DD / 4) return;
    float4 v = ((const float4*)s)[i];
    __nv_bfloat16 h0, h1, h2, h3, l0, l1, l2, l3;
    split2(v.x, h0, l0); split2(v.y, h1, l1);
    split2(v.z, h2, l2); split2(v.w, h3, l3);
    uint2 uh, ul;
    uh.x = (uint32_t)__bfloat16_as_ushort(h0) | ((uint32_t)__bfloat16_as_ushort(h1) << 16);
    uh.y = (uint32_t)__bfloat16_as_ushort(h2) | ((uint32_t)__bfloat16_as_ushort(h3) << 16);
    ul.x = (uint32_t)__bfloat16_as_ushort(l0) | ((uint32_t)__bfloat16_as_ushort(l1) << 16);
    ul.y = (uint32_t)__bfloat16_as_ushort(l2) | ((uint32_t)__bfloat16_as_ushort(l3) << 16);
    ((uint2*)g_ah[slot])[i] = uh;
    ((uint2*)g_al[slot])[i] = ul;
}

// W[k][n] -> W^T[n][k] bf16 hi/lo, tiled transpose. grid (16,16,4), block (32,8)
__global__ __launch_bounds__(256) void transpose_split_kernel(const float* __restrict__ Wq,
                                                              const float* __restrict__ Wk,
                                                              const float* __restrict__ Wv,
                                                              const float* __restrict__ Wo)
{
    __shared__ float tile[32][33];
    const int z = blockIdx.z;
    const float* W = (z == 0) ? Wq : (z == 1) ? Wk : (z == 2) ? Wv : Wo;
    const int k0 = blockIdx.y * 32, n0 = blockIdx.x * 32;
#pragma unroll
    for (int r = 0; r < 32; r += 8)
        tile[threadIdx.y + r][threadIdx.x] = W[(size_t)(k0 + threadIdx.y + r) * DD + n0 + threadIdx.x];
    __syncthreads();
#pragma unroll
    for (int r = 0; r < 32; r += 8) {
        const int n = n0 + threadIdx.y + r, k = k0 + threadIdx.x;
        __nv_bfloat16 h, l;
        split2(tile[threadIdx.x][threadIdx.y + r], h, l);
        g_wh[z][(size_t)n * DD + k] = h;
        g_wl[z][(size_t)n * DD + k] = l;
    }
}

// =========================== HMMA GEMM =====================================
// C[8192,512] = A @ W + bias via bf16 3-term split (AhBh + AhBl + AlBh).
// CTA 128x128, 8 warps (2x4), warp tile 64x32, BK=32, 2-stage cp.async.
#define STG 40                       // smem row stride in bf16 elems (conflict-free)
#define ARR_E (128*STG)              // 5120 elems per array
#define ARR_B (ARR_E*2)              // 10240 bytes
#define STAGE_B (4*ARR_B)            // 40960 bytes per stage
#define GSMEM (2*STAGE_B)            // 81920 total

struct GemmPtrs {
    const __nv_bfloat16 *Ah, *Al, *Bh, *Bl;
};

__device__ __forceinline__ void gemm_load_chunk(const GemmPtrs& P, uint32_t sbase,
                                                int stage, int m0, int n0, int k0, int tid)
{
    const uint32_t s = sbase + stage * STAGE_B;
#pragma unroll
    for (int rep = 0; rep < 2; rep++) {
        const int c = tid + rep * 256;
        const int row = c >> 2;
        const int kp = (c & 3) * 8;
        const uint32_t so = (uint32_t)(row * STG + kp) * 2;
        cpasync16(s + so,             P.Ah + (size_t)(m0 + row) * DD + k0 + kp);
        cpasync16(s + ARR_B + so,     P.Al + (size_t)(m0 + row) * DD + k0 + kp);
        cpasync16(s + 2*ARR_B + so,   P.Bh + (size_t)(n0 + row) * DD + k0 + kp);
        cpasync16(s + 3*ARR_B + so,   P.Bl + (size_t)(n0 + row) * DD + k0 + kp);
    }
    cp_commit();
}

// SCATTER=0: row-major dst[m][512]; SCATTER=1: (B,H,L,DK) layout
template<int SCATTER>
__device__ __forceinline__ void gemm_core(const GemmPtrs& P, const float* __restrict__ bias,
                                          float* __restrict__ dst, char* smraw)
{
    const int tid = threadIdx.x;
    const int m0 = blockIdx.y * 128, n0 = blockIdx.x * 128;
    const uint32_t sbase = smem_u32(smraw);
    const __nv_bfloat16* smb = (const __nv_bfloat16*)smraw;

    const int wid = tid >> 5, lane = tid & 31;
    const int wm = (wid >> 2) * 64;       // 0 or 64
    const int wn = (wid & 3) * 32;        // 0,32,64,96
    const int g  = lane >> 2;             // 0..7
    const int q2 = (lane & 3) * 2;        // 0,2,4,6

    float acc[4][4][4];
#pragma unroll
    for (int i = 0; i < 4; i++)
#pragma unroll
        for (int j = 0; j < 4; j++)
#pragma unroll
            for (int r = 0; r < 4; r++) acc[i][j][r] = 0.f;

    gemm_load_chunk(P, sbase, 0, m0, n0, 0, tid);

    for (int c = 0; c < 16; c++) {
        const int st = c & 1;
        if (c < 15) {
            gemm_load_chunk(P, sbase, st ^ 1, m0, n0, (c + 1) * 32, tid);
            cp_wait<1>();
        } else {
            cp_wait<0>();
        }
        __syncthreads();

        const __nv_bfloat16* sAh = smb + st * (STAGE_B / 2);
        const __nv_bfloat16* sAl = sAh + ARR_E;
        const __nv_bfloat16* sBh = sAh + 2 * ARR_E;
        const __nv_bfloat16* sBl = sAh + 3 * ARR_E;

#pragma unroll
        for (int ks = 0; ks < 32; ks += 16) {
            uint32_t af[4][4], bfh[4][2], bfl[4][2];
#pragma unroll
            for (int i = 0; i < 4; i++) {
                const int r0 = wm + i * 16 + g;
                af[i][0] = *(const uint32_t*)(sAh + r0 * STG + ks + q2);
                af[i][1] = *(const uint32_t*)(sAh + (r0 + 8) * STG + ks + q2);
                af[i][2] = *(const uint32_t*)(sAh + r0 * STG + ks + 8 + q2);
                af[i][3] = *(const uint32_t*)(sAh + (r0 + 8) * STG + ks + 8 + q2);
            }
#pragma unroll
            for (int j = 0; j < 4; j++) {
                const int n = wn + j * 8 + g;
                bfh[j][0] = *(const uint32_t*)(sBh + n * STG + ks + q2);
                bfh[j][1] = *(const uint32_t*)(sBh + n * STG + ks + 8 + q2);
                bfl[j][0] = *(const uint32_t*)(sBl + n * STG + ks + q2);
                bfl[j][1] = *(const uint32_t*)(sBl + n * STG + ks + 8 + q2);
            }
#pragma unroll
            for (int i = 0; i < 4; i++)
#pragma unroll
                for (int j = 0; j < 4; j++)
                    mma_bf16(acc[i][j][0], acc[i][j][1], acc[i][j][2], acc[i][j][3],
                             af[i][0], af[i][1], af[i][2], af[i][3], bfh[j][0], bfh[j][1]);
#pragma unroll
            for (int i = 0; i < 4; i++)
#pragma unroll
                for (int j = 0; j < 4; j++)
                    mma_bf16(acc[i][j][0], acc[i][j][1], acc[i][j][2], acc[i][j][3],
                             af[i][0], af[i][1], af[i][2], af[i][3], bfl[j][0], bfl[j][1]);
#pragma unroll
            for (int i = 0; i < 4; i++) {           // reload A from Al
                const int r0 = wm + i * 16 + g;
                af[i][0] = *(const uint32_t*)(sAl + r0 * STG + ks + q2);
                af[i][1] = *(const uint32_t*)(sAl + (r0 + 8) * STG + ks + q2);
                af[i][2] = *(const uint32_t*)(sAl + r0 * STG + ks + 8 + q2);
                af[i][3] = *(const uint32_t*)(sAl + (r0 + 8) * STG + ks + 8 + q2);
            }
#pragma unroll
            for (int i = 0; i < 4; i++)
#pragma unroll
                for (int j = 0; j < 4; j++)
                    mma_bf16(acc[i][j][0], acc[i][j][1], acc[i][j][2], acc[i][j][3],
                             af[i][0], af[i][1], af[i][2], af[i][3], bfh[j][0], bfh[j][1]);
        }
        __syncthreads();
    }

    // epilogue
#pragma unroll
    for (int i = 0; i < 4; i++) {
#pragma unroll
        for (int j = 0; j < 4; j++) {
            const int gm0 = m0 + wm + i * 16 + g;
            const int gn  = n0 + wn + j * 8 + q2;
            const float b0 = bias[gn], b1 = bias[gn + 1];
            const float v0 = acc[i][j][0] + b0, v1 = acc[i][j][1] + b1;
            const float v2 = acc[i][j][2] + b0, v3 = acc[i][j][3] + b1;
            if (SCATTER == 0) {
                float* p0 = dst + (size_t)gm0 * DD + gn;
                p0[0] = v0; p0[1] = v1;
                float* p1 = dst + (size_t)(gm0 + 8) * DD + gn;
                p1[0] = v2; p1[1] = v3;
            } else {
                const int h = gn >> 6, dk = gn & 63;
                {
                    const int b = gm0 >> 11, l = gm0 & 2047;
                    float* p = dst + (((size_t)(b * HH + h)) * LL + l) * DKK + dk;
                    p[0] = v0; p[1] = v1;
                }
                {
                    const int gm1 = gm0 + 8;
                    const int b = gm1 >> 11, l = gm1 & 2047;
                    float* p = dst + (((size_t)(b * HH + h)) * LL + l) * DKK + dk;
                    p[0] = v2; p[1] = v3;
                }
            }
        }
    }
}

__global__ __launch_bounds__(256, 1) void hgemm_qkv(const float* __restrict__ bq,
                                                    const float* __restrict__ bk,
                                                    const float* __restrict__ bv)
{
    extern __shared__ char smraw[];
    const int z = blockIdx.z;
    GemmPtrs P;
    P.Ah = g_ah[z]; P.Al = g_al[z]; P.Bh = g_wh[z]; P.Bl = g_wl[z];
    const float* bias = (z == 0) ? bq : (z == 1) ? bk : bv;
    float* dst = (z == 0) ? g_q : (z == 1) ? g_k : g_v;
    gemm_core<1>(P, bias, dst, smraw);
}

__global__ __launch_bounds__(256, 1) void hgemm_out(const float* __restrict__ bo,
                                                    float* __restrict__ outp)
{
    extern __shared__ char smraw[];
    GemmPtrs P;
    P.Ah = g_ah[0]; P.Al = g_al[0]; P.Bh = g_wh[3]; P.Bl = g_wl[3];
    gemm_core<0>(P, bo, outp, smraw);
}

// =========================== non-GEMM kernels ==============================
__global__ __launch_bounds__(256) void probe_kernel(const int* __restrict__ idx)
{
    const int w = (blockIdx.x * blockDim.x + threadIdx.x) >> 5;
    const int lane = threadIdx.x & 31;
    if (w >= BB * HH * LL) return;
    const int l = w & (LL - 1);
    const int bh = w >> 11;

    const float* qrow = g_q + (size_t)(bh * LL + l) * DKK;
    const float q0 = qrow[lane];
    const float q1 = qrow[lane + 32];
    const float* kbase = g_k + (size_t)bh * LL * DKK;
    const int* ip = idx + l * UU;

    float mx = -INFINITY, sm = 0.f;
#pragma unroll 4
    for (int s = 0; s < UU; s++) {
        const int j = ip[s];
        const float* kr = kbase + (size_t)j * DKK;
        float p = q0 * kr[lane] + q1 * kr[lane + 32];
#pragma unroll
        for (int o = 16; o > 0; o >>= 1) p += __shfl_xor_sync(0xffffffffu, p, o);
        mx = fmaxf(mx, p);
        sm += p;
    }
    if (lane == 0) g_m[w] = mx - sm * (1.0f / LL);
}

__global__ __launch_bounds__(256) void topk_kernel()
{
    __shared__ float vals[LL];
    __shared__ float rv[256];
    __shared__ int   ri[256];
    const int bh = blockIdx.x;
    const int t = threadIdx.x;

    for (int i = t; i < LL; i += 256) vals[i] = g_m[(size_t)bh * LL + i];
    __syncthreads();

    for (int iter = 0; iter < UU; iter++) {
        float bestv = -INFINITY; int besti = 0;
        for (int i = t; i < LL; i += 256) {
            const float v = vals[i];
            if (v > bestv) { bestv = v; besti = i; }
        }
        rv[t] = bestv; ri[t] = besti;
        __syncthreads();
        for (int s = 128; s > 0; s >>= 1) {
            if (t < s) {
                if (rv[t + s] > rv[t] ||
                    (rv[t + s] == rv[t] && ri[t + s] < ri[t])) {
                    rv[t] = rv[t + s]; ri[t] = ri[t + s];
                }
            }
            __syncthreads();
        }
        if (t == 0) {
            g_top[bh * UU + iter] = ri[0];
            vals[ri[0]] = -INFINITY;
        }
        __syncthreads();
    }
}

__global__ __launch_bounds__(256) void attn_kernel()
{
    __shared__ float sc[LL];
    __shared__ float qs[DKK];
    __shared__ float red[256];

    const int blk = blockIdx.x;
    const int bh = blk / UU;
    const int t = threadIdx.x;
    const int pos = g_top[blk];

    const float* kb = g_k + (size_t)bh * LL * DKK;
    const float* vb = g_v + (size_t)bh * LL * DKK;

    if (t < DKK) qs[t] = g_q[((size_t)bh * LL + pos) * DKK + t];
    __syncthreads();

    const float scale = rsqrtf((float)DD);

    float lmax = -INFINITY;
    for (int j = t; j < LL; j += 256) {
        const float* kr = kb + (size_t)j * DKK;
        float dot = 0.f;
#pragma unroll
        for (int d = 0; d < DKK; d++) dot += qs[d] * kr[d];
        const float s = (j > pos) ? -INFINITY : dot * scale;
        sc[j] = s;
        lmax = fmaxf(lmax, s);
    }
    red[t] = lmax; __syncthreads();
    for (int s = 128; s > 0; s >>= 1) {
        if (t < s) red[t] = fmaxf(red[t], red[t + s]);
        __syncthreads();
    }
    const float mx = red[0];
    __syncthreads();

    float lsum = 0.f;
    for (int j = t; j < LL; j += 256) {
        const float p = expf(sc[j] - mx);
        sc[j] = p;
        lsum += p;
    }
    red[t] = lsum; __syncthreads();
    for (int s = 128; s > 0; s >>= 1) {
        if (t < s) red[t] += red[t + s];
        __syncthreads();
    }
    const float inv = 1.0f / red[0];
    __syncthreads();

    const int d = t & 63;
    const int g = t >> 6;
    float acc = 0.f;
    const int j0 = g * (LL / 4), j1 = j0 + (LL / 4);
    for (int j = j0; j < j1; j++) acc += sc[j] * vb[(size_t)j * DKK + d];
    red[t] = acc; __syncthreads();
    if (t < DKK) {
        const float o = (red[t] + red[t + 64] + red[t + 128] + red[t + 192]) * inv;
        g_att[(size_t)blk * DKK + t] = o;
    }
}

__global__ __launch_bounds__(256) void cumsum_kernel()
{
    __shared__ float part[4][DKK];
    const int bh = blockIdx.x;
    const int b = bh >> 3, h = bh & 7;
    const int t = threadIdx.x;
    const int d = t & 63, c = t >> 6;
    const float* vb = g_v + (size_t)bh * LL * DKK;

    const int l0 = c * (LL / 4), l1 = l0 + (LL / 4);
    float s = 0.f;
    for (int l = l0; l < l1; l++) s += vb[(size_t)l * DKK + d];
    part[c][d] = s;
    __syncthreads();

    float off = 0.f;
    for (int cc = 0; cc < c; cc++) off += part[cc][d];

    float acc = off;
    float* cb = g_ctx + (size_t)b * LL * DD + h * DKK;
    for (int l = l0; l < l1; l++) {
        acc += vb[(size_t)l * DKK + d];
        cb[(size_t)l * DD + d] = acc;
    }
}

__global__ void scatter_kernel()
{
    const int i = blockIdx.x * blockDim.x + threadIdx.x;
    if (i >= BB * HH * UU * DKK) return;
    const int d = i & 63;
    const int r = i >> 6;
    const int bh = r / UU;
    const int b = bh >> 3, h = bh & 7;
    const int pos = g_top[r];
    g_ctx[((size_t)b * LL + pos) * DD + h * DKK + d] = g_att[i];
}

// ---------------------------------------------------------------------------
extern "C" void kernel_launch(void* const* d_in, const int* in_sizes, int n_in,
                              void* d_out, int out_size)
{
    const float* queries = (const float*)d_in[0];
    const float* keys    = (const float*)d_in[1];
    const float* values  = (const float*)d_in[2];
    const int*   index_sample = (const int*)d_in[3];
    const float* Wq = (const float*)d_in[4];
    const float* bq = (const float*)d_in[5];
    const float* Wk = (const float*)d_in[6];
    const float* bk = (const float*)d_in[7];
    const float* Wv = (const float*)d_in[8];
    const float* bv = (const float*)d_in[9];
    const float* Wo = (const float*)d_in[10];
    const float* bo = (const float*)d_in[11];
    float* out = (float*)d_out;

    static int configured = 0;
    if (!configured) {
        cudaFuncSetAttribute(hgemm_qkv, cudaFuncAttributeMaxDynamicSharedMemorySize, GSMEM);
        cudaFuncSetAttribute(hgemm_out, cudaFuncAttributeMaxDynamicSharedMemorySize, GSMEM);
        configured = 1;
    }

    const int cvt_blocks = (MTOT * DD / 4 + 255) / 256;
    convert_split_kernel<<<cvt_blocks, 256>>>(queries, 0);
    convert_split_kernel<<<cvt_blocks, 256>>>(keys,    1);
    convert_split_kernel<<<cvt_blocks, 256>>>(values,  2);
    transpose_split_kernel<<<dim3(16, 16, 4), dim3(32, 8)>>>(Wq, Wk, Wv, Wo);

    hgemm_qkv<<<dim3(DD / 128, MTOT / 128, 3), 256, GSMEM>>>(bq, bk, bv);

    probe_kernel<<<(BB * HH * LL * 32) / 256, 256>>>(index_sample);
    topk_kernel<<<BH, 256>>>();
    attn_kernel<<<BH * UU, 256>>>();
    cumsum_kernel<<<BH, 256>>>();
    scatter_kernel<<<(BB * HH * UU * DKK + 255) / 256, 256>>>();

    convert_split_kernel<<<cvt_blocks, 256>>>(nullptr, 0);   // g_ctx -> slot 0
    hgemm_out<<<dim3(DD / 128, MTOT / 128, 1), 256, GSMEM>>>(bo, out);
}

// round 6
// speedup vs baseline: 2.0939x; 1.5868x over previous
#include <cuda_runtime.h>
#include <cuda_bf16.h>
#include <math.h>
#include <stdint.h>

// Problem constants
#define BB 4
#define LL 2048
#define DD 512
#define HH 8
#define DKK 64
#define UU 24
#define BH (BB*HH)
#define MTOT (BB*LL)     // 8192 rows per GEMM

// ---------------- scratch (device globals; no allocation allowed) ----------
__device__ float g_q[BB*HH*LL*DKK];     // (B,H,L,DK)
__device__ float g_k[BB*HH*LL*DKK];
__device__ float g_v[BB*HH*LL*DKK];
__device__ float g_m[BB*HH*LL];
__device__ int   g_top[BB*HH*UU];
__device__ float g_att[BB*HH*UU*DKK];
__device__ float g_ctx[BB*LL*DD];       // (b, l, h*DK+dk)

// pre-split transposed weights W^T[n][k] in bf16 hi/lo (Wq,Wk,Wv,Wo)
__device__ __nv_bfloat16 g_wh[4][DD*DD];
__device__ __nv_bfloat16 g_wl[4][DD*DD];

// =========================== helpers =======================================
__device__ __forceinline__ uint32_t smem_u32(const void* p) {
    uint32_t a;
    asm("{ .reg .u64 t; cvta.to.shared.u64 t, %1; cvt.u32.u64 %0, t; }"
        : "=r"(a) : "l"(p));
    return a;
}
__device__ __forceinline__ void cpasync16(uint32_t saddr, const void* gptr) {
    asm volatile("cp.async.cg.shared.global [%0], [%1], 16;"
                 :: "r"(saddr), "l"(__cvta_generic_to_global(gptr)) : "memory");
}
__device__ __forceinline__ void cp_commit() {
    asm volatile("cp.async.commit_group;" ::: "memory");
}
template<int N>
__device__ __forceinline__ void cp_wait() {
    asm volatile("cp.async.wait_group %0;" :: "n"(N) : "memory");
}
__device__ __forceinline__ void mma_bf16(float& c0, float& c1, float& c2, float& c3,
                                         uint32_t a0, uint32_t a1, uint32_t a2, uint32_t a3,
                                         uint32_t b0, uint32_t b1) {
    asm volatile("mma.sync.aligned.m16n8k16.row.col.f32.bf16.bf16.f32 "
                 "{%0,%1,%2,%3}, {%4,%5,%6,%7}, {%8,%9}, {%0,%1,%2,%3};"
                 : "+f"(c0), "+f"(c1), "+f"(c2), "+f"(c3)
                 : "r"(a0), "r"(a1), "r"(a2), "r"(a3), "r"(b0), "r"(b1));
}
__device__ __forceinline__ void split2(float x, __nv_bfloat16& h, __nv_bfloat16& l) {
    h = __float2bfloat16_rn(x);
    l = __float2bfloat16_rn(x - __bfloat162float(h));
}
__device__ __forceinline__ uint32_t pack2(__nv_bfloat16 a, __nv_bfloat16 b) {
    return (uint32_t)__bfloat16_as_ushort(a) | ((uint32_t)__bfloat16_as_ushort(b) << 16);
}

// W[k][n] -> W^T[n][k] bf16 hi/lo, tiled transpose. grid (16,16,4), block (32,8)
__global__ __launch_bounds__(256) void transpose_split_kernel(const float* __restrict__ Wq,
                                                              const float* __restrict__ Wk,
                                                              const float* __restrict__ Wv,
                                                              const float* __restrict__ Wo)
{
    __shared__ float tile[32][33];
    const int z = blockIdx.z;
    const float* W = (z == 0) ? Wq : (z == 1) ? Wk : (z == 2) ? Wv : Wo;
    const int k0 = blockIdx.y * 32, n0 = blockIdx.x * 32;
#pragma unroll
    for (int r = 0; r < 32; r += 8)
        tile[threadIdx.y + r][threadIdx.x] = W[(size_t)(k0 + threadIdx.y + r) * DD + n0 + threadIdx.x];
    __syncthreads();
#pragma unroll
    for (int r = 0; r < 32; r += 8) {
        const int n = n0 + threadIdx.y + r, k = k0 + threadIdx.x;
        __nv_bfloat16 h, l;
        split2(tile[threadIdx.x][threadIdx.y + r], h, l);
        g_wh[z][(size_t)n * DD + k] = h;
        g_wl[z][(size_t)n * DD + k] = l;
    }
}

// =========================== HMMA GEMM (fused split) =======================
// C[8192,512] = A(fp32) @ W + bias via bf16 3-term split (AhBh + AhBl + AlBh).
// A is cp.async'd as fp32 into smem and split->bf16 in-smem each chunk.
// CTA 128x128, 8 warps (2x4), warp tile 64x32, BK=32, 2-stage pipeline.
#define STG 40                        // smem row stride, bf16 elems
#define ARR_E (128*STG)               // 5120 elems
#define ARR_B (ARR_E*2)               // 10240 bytes
#define AF_STRIDE 36                  // fp32 stage row stride, floats
#define AF_B (128*AF_STRIDE*4)        // 18432 bytes
#define OFF_AF 0
#define OFF_AH (AF_B)                 // 18432
#define OFF_AL (OFF_AH + ARR_B)       // 28672
#define OFF_BH (OFF_AL + ARR_B)       // 38912
#define OFF_BL (OFF_BH + ARR_B)       // 49152
#define STAGE_B (OFF_BL + ARR_B)      // 59392
#define GSMEM (2*STAGE_B)             // 118784

__device__ __forceinline__ void gemm_load_chunk(const float* __restrict__ A,
                                                const __nv_bfloat16* __restrict__ Bh,
                                                const __nv_bfloat16* __restrict__ Bl,
                                                uint32_t sbase, int stage,
                                                int m0, int n0, int k0, int tid)
{
    const uint32_t s = sbase + stage * STAGE_B;
    // A fp32: 128 rows x 32 floats = 1024 x 16B
#pragma unroll
    for (int rep = 0; rep < 4; rep++) {
        const int c = tid + rep * 256;
        const int row = c >> 3, kp = (c & 7) * 4;
        cpasync16(s + OFF_AF + (uint32_t)(row * AF_STRIDE + kp) * 4,
                  A + (size_t)(m0 + row) * DD + k0 + kp);
    }
    // Bh/Bl: 128 rows x 32 bf16 = 512 x 16B each
#pragma unroll
    for (int rep = 0; rep < 2; rep++) {
        const int c = tid + rep * 256;
        const int row = c >> 2, kp = (c & 3) * 8;
        cpasync16(s + OFF_BH + (uint32_t)(row * STG + kp) * 2,
                  Bh + (size_t)(n0 + row) * DD + k0 + kp);
    }
#pragma unroll
    for (int rep = 0; rep < 2; rep++) {
        const int c = tid + rep * 256;
        const int row = c >> 2, kp = (c & 3) * 8;
        cpasync16(s + OFF_BL + (uint32_t)(row * STG + kp) * 2,
                  Bl + (size_t)(n0 + row) * DD + k0 + kp);
    }
    cp_commit();
}

// SCATTER=0: row-major dst[m][512]; SCATTER=1: (B,H,L,DK) layout
template<int SCATTER>
__device__ __forceinline__ void gemm_core(const float* __restrict__ A,
                                          const __nv_bfloat16* __restrict__ Bh,
                                          const __nv_bfloat16* __restrict__ Bl,
                                          const float* __restrict__ bias,
                                          float* __restrict__ dst, char* smraw)
{
    const int tid = threadIdx.x;
    const int m0 = blockIdx.y * 128, n0 = blockIdx.x * 128;
    const uint32_t sbase = smem_u32(smraw);

    const int wid = tid >> 5, lane = tid & 31;
    const int wm = (wid >> 2) * 64;       // 0 or 64
    const int wn = (wid & 3) * 32;        // 0,32,64,96
    const int g  = lane >> 2;             // 0..7
    const int q2 = (lane & 3) * 2;        // 0,2,4,6

    float acc[4][4][4];
#pragma unroll
    for (int i = 0; i < 4; i++)
#pragma unroll
        for (int j = 0; j < 4; j++)
#pragma unroll
            for (int r = 0; r < 4; r++) acc[i][j][r] = 0.f;

    gemm_load_chunk(A, Bh, Bl, sbase, 0, m0, n0, 0, tid);

    for (int c = 0; c < 16; c++) {
        const int st = c & 1;
        if (c < 15) {
            gemm_load_chunk(A, Bh, Bl, sbase, st ^ 1, m0, n0, (c + 1) * 32, tid);
            cp_wait<1>();
        } else {
            cp_wait<0>();
        }
        __syncthreads();

        // in-smem split: Af32(st) -> Ah(st), Al(st). 16 floats per thread.
        {
            char* sp = smraw + st * STAGE_B;
            const float* af = (const float*)(sp + OFF_AF);
            __nv_bfloat16* ah = (__nv_bfloat16*)(sp + OFF_AH);
            __nv_bfloat16* al = (__nv_bfloat16*)(sp + OFF_AL);
            const int row = tid >> 1, half = (tid & 1) * 16;
#pragma unroll
            for (int qq = 0; qq < 4; qq++) {
                float4 v = *(const float4*)(af + row * AF_STRIDE + half + qq * 4);
                __nv_bfloat16 h0, h1, h2, h3, l0, l1, l2, l3;
                split2(v.x, h0, l0); split2(v.y, h1, l1);
                split2(v.z, h2, l2); split2(v.w, h3, l3);
                uint2 uh = { pack2(h0, h1), pack2(h2, h3) };
                uint2 ul = { pack2(l0, l1), pack2(l2, l3) };
                *(uint2*)(ah + row * STG + half + qq * 4) = uh;
                *(uint2*)(al + row * STG + half + qq * 4) = ul;
            }
        }
        __syncthreads();

        const __nv_bfloat16* sAh = (const __nv_bfloat16*)(smraw + st * STAGE_B + OFF_AH);
        const __nv_bfloat16* sAl = (const __nv_bfloat16*)(smraw + st * STAGE_B + OFF_AL);
        const __nv_bfloat16* sBh = (const __nv_bfloat16*)(smraw + st * STAGE_B + OFF_BH);
        const __nv_bfloat16* sBl = (const __nv_bfloat16*)(smraw + st * STAGE_B + OFF_BL);

#pragma unroll
        for (int ks = 0; ks < 32; ks += 16) {
            uint32_t af[4][4], bfh[4][2], bfl[4][2];
#pragma unroll
            for (int i = 0; i < 4; i++) {
                const int r0 = wm + i * 16 + g;
                af[i][0] = *(const uint32_t*)(sAh + r0 * STG + ks + q2);
                af[i][1] = *(const uint32_t*)(sAh + (r0 + 8) * STG + ks + q2);
                af[i][2] = *(const uint32_t*)(sAh + r0 * STG + ks + 8 + q2);
                af[i][3] = *(const uint32_t*)(sAh + (r0 + 8) * STG + ks + 8 + q2);
            }
#pragma unroll
            for (int j = 0; j < 4; j++) {
                const int n = wn + j * 8 + g;
                bfh[j][0] = *(const uint32_t*)(sBh + n * STG + ks + q2);
                bfh[j][1] = *(const uint32_t*)(sBh + n * STG + ks + 8 + q2);
                bfl[j][0] = *(const uint32_t*)(sBl + n * STG + ks + q2);
                bfl[j][1] = *(const uint32_t*)(sBl + n * STG + ks + 8 + q2);
            }
#pragma unroll
            for (int i = 0; i < 4; i++)
#pragma unroll
                for (int j = 0; j < 4; j++)
                    mma_bf16(acc[i][j][0], acc[i][j][1], acc[i][j][2], acc[i][j][3],
                             af[i][0], af[i][1], af[i][2], af[i][3], bfh[j][0], bfh[j][1]);
#pragma unroll
            for (int i = 0; i < 4; i++)
#pragma unroll
                for (int j = 0; j < 4; j++)
                    mma_bf16(acc[i][j][0], acc[i][j][1], acc[i][j][2], acc[i][j][3],
                             af[i][0], af[i][1], af[i][2], af[i][3], bfl[j][0], bfl[j][1]);
#pragma unroll
            for (int i = 0; i < 4; i++) {           // reload A from Al
                const int r0 = wm + i * 16 + g;
                af[i][0] = *(const uint32_t*)(sAl + r0 * STG + ks + q2);
                af[i][1] = *(const uint32_t*)(sAl + (r0 + 8) * STG + ks + q2);
                af[i][2] = *(const uint32_t*)(sAl + r0 * STG + ks + 8 + q2);
                af[i][3] = *(const uint32_t*)(sAl + (r0 + 8) * STG + ks + 8 + q2);
            }
#pragma unroll
            for (int i = 0; i < 4; i++)
#pragma unroll
                for (int j = 0; j < 4; j++)
                    mma_bf16(acc[i][j][0], acc[i][j][1], acc[i][j][2], acc[i][j][3],
                             af[i][0], af[i][1], af[i][2], af[i][3], bfh[j][0], bfh[j][1]);
        }
        __syncthreads();
    }

    // epilogue
#pragma unroll
    for (int i = 0; i < 4; i++) {
#pragma unroll
        for (int j = 0; j < 4; j++) {
            const int gm0 = m0 + wm + i * 16 + g;
            const int gn  = n0 + wn + j * 8 + q2;
            const float b0 = bias[gn], b1 = bias[gn + 1];
            const float v0 = acc[i][j][0] + b0, v1 = acc[i][j][1] + b1;
            const float v2 = acc[i][j][2] + b0, v3 = acc[i][j][3] + b1;
            if (SCATTER == 0) {
                float* p0 = dst + (size_t)gm0 * DD + gn;
                p0[0] = v0; p0[1] = v1;
                float* p1 = dst + (size_t)(gm0 + 8) * DD + gn;
                p1[0] = v2; p1[1] = v3;
            } else {
                const int h = gn >> 6, dk = gn & 63;
                {
                    const int b = gm0 >> 11, l = gm0 & 2047;
                    float* p = dst + (((size_t)(b * HH + h)) * LL + l) * DKK + dk;
                    p[0] = v0; p[1] = v1;
                }
                {
                    const int gm1 = gm0 + 8;
                    const int b = gm1 >> 11, l = gm1 & 2047;
                    float* p = dst + (((size_t)(b * HH + h)) * LL + l) * DKK + dk;
                    p[0] = v2; p[1] = v3;
                }
            }
        }
    }
}

__global__ __launch_bounds__(256, 1) void hgemm_qkv(const float* __restrict__ q,
                                                    const float* __restrict__ k,
                                                    const float* __restrict__ v,
                                                    const float* __restrict__ bq,
                                                    const float* __restrict__ bk,
                                                    const float* __restrict__ bv)
{
    extern __shared__ char smraw[];
    const int z = blockIdx.z;
    const float* A = (z == 0) ? q : (z == 1) ? k : v;
    const float* bias = (z == 0) ? bq : (z == 1) ? bk : bv;
    float* dst = (z == 0) ? g_q : (z == 1) ? g_k : g_v;
    gemm_core<1>(A, g_wh[z], g_wl[z], bias, dst, smraw);
}

__global__ __launch_bounds__(256, 1) void hgemm_out(const float* __restrict__ bo,
                                                    float* __restrict__ outp)
{
    extern __shared__ char smraw[];
    gemm_core<0>((const float*)g_ctx, g_wh[3], g_wl[3], bo, outp, smraw);
}

// =========================== non-GEMM kernels ==============================
__global__ __launch_bounds__(256) void probe_kernel(const int* __restrict__ idx)
{
    const int w = (blockIdx.x * blockDim.x + threadIdx.x) >> 5;
    const int lane = threadIdx.x & 31;
    if (w >= BB * HH * LL) return;
    const int l = w & (LL - 1);
    const int bh = w >> 11;

    const float* qrow = g_q + (size_t)(bh * LL + l) * DKK;
    const float q0 = qrow[lane];
    const float q1 = qrow[lane + 32];
    const float* kbase = g_k + (size_t)bh * LL * DKK;
    const int* ip = idx + l * UU;

    float mx = -INFINITY, sm = 0.f;
#pragma unroll 4
    for (int s = 0; s < UU; s++) {
        const int j = ip[s];
        const float* kr = kbase + (size_t)j * DKK;
        float p = q0 * kr[lane] + q1 * kr[lane + 32];
#pragma unroll
        for (int o = 16; o > 0; o >>= 1) p += __shfl_xor_sync(0xffffffffu, p, o);
        mx = fmaxf(mx, p);
        sm += p;
    }
    if (lane == 0) g_m[w] = mx - sm * (1.0f / LL);
}

__global__ __launch_bounds__(256) void topk_kernel()
{
    __shared__ float vals[LL];
    __shared__ float rv[256];
    __shared__ int   ri[256];
    const int bh = blockIdx.x;
    const int t = threadIdx.x;

    for (int i = t; i < LL; i += 256) vals[i] = g_m[(size_t)bh * LL + i];
    __syncthreads();

    for (int iter = 0; iter < UU; iter++) {
        float bestv = -INFINITY; int besti = 0;
        for (int i = t; i < LL; i += 256) {
            const float v = vals[i];
            if (v > bestv) { bestv = v; besti = i; }
        }
        rv[t] = bestv; ri[t] = besti;
        __syncthreads();
        for (int s = 128; s > 0; s >>= 1) {
            if (t < s) {
                if (rv[t + s] > rv[t] ||
                    (rv[t + s] == rv[t] && ri[t + s] < ri[t])) {
                    rv[t] = rv[t + s]; ri[t] = ri[t + s];
                }
            }
            __syncthreads();
        }
        if (t == 0) {
            g_top[bh * UU + iter] = ri[0];
            vals[ri[0]] = -INFINITY;
        }
        __syncthreads();
    }
}

// Batched sparse attention: one block per (bh, group of 4 top queries).
// Scores for 4 queries kept in smem; K and V each read once per block.
#define QG 4
__global__ __launch_bounds__(256) void attn_kernel()
{
    __shared__ float qs[QG][DKK];
    __shared__ float sc[QG][LL];        // 32 KB
    __shared__ float red[256];
    __shared__ int   pos_s[QG];

    const int bh = blockIdx.x / (UU / QG);
    const int grp = blockIdx.x % (UU / QG);
    const int t = threadIdx.x;
    const int wid = t >> 5, lane = t & 31;

    const float* kb = g_k + (size_t)bh * LL * DKK;
    const float* vb = g_v + (size_t)bh * LL * DKK;

    {
        const int u = t >> 6, d = t & 63;      // 256 = 4*64 exactly
        const int p = g_top[bh * UU + grp * QG + u];
        if (d == 0) pos_s[u] = p;
        qs[u][d] = g_q[((size_t)bh * LL + p) * DKK + d];
    }
    __syncthreads();

    const float scale = rsqrtf((float)DD);

    float lmax[QG];
#pragma unroll
    for (int u = 0; u < QG; u++) lmax[u] = -INFINITY;

    for (int j = t; j < LL; j += 256) {
        const float* kr = kb + (size_t)j * DKK;
        float dot[QG];
#pragma unroll
        for (int u = 0; u < QG; u++) dot[u] = 0.f;
#pragma unroll
        for (int d4 = 0; d4 < 16; d4++) {
            float4 kk = *(const float4*)(kr + d4 * 4);
#pragma unroll
            for (int u = 0; u < QG; u++) {
                dot[u] += qs[u][d4 * 4] * kk.x + qs[u][d4 * 4 + 1] * kk.y +
                          qs[u][d4 * 4 + 2] * kk.z + qs[u][d4 * 4 + 3] * kk.w;
            }
        }
#pragma unroll
        for (int u = 0; u < QG; u++) {
            const float s = (j > pos_s[u]) ? -INFINITY : dot[u] * scale;
            sc[u][j] = s;
            lmax[u] = fmaxf(lmax[u], s);
        }
    }
    // block-reduce maxes: warp shuffle then 8 partials in smem per u
#pragma unroll
    for (int u = 0; u < QG; u++) {
        float m = lmax[u];
#pragma unroll
        for (int o = 16; o > 0; o >>= 1) m = fmaxf(m, __shfl_xor_sync(0xffffffffu, m, o));
        if (lane == 0) red[u * 8 + wid] = m;
    }
    __syncthreads();
    float mx[QG];
#pragma unroll
    for (int u = 0; u < QG; u++) {
        float m = -INFINITY;
#pragma unroll
        for (int w = 0; w < 8; w++) m = fmaxf(m, red[u * 8 + w]);
        mx[u] = m;
    }
    __syncthreads();

    float lsum[QG];
#pragma unroll
    for (int u = 0; u < QG; u++) lsum[u] = 0.f;
    for (int j = t; j < LL; j += 256) {
#pragma unroll
        for (int u = 0; u < QG; u++) {
            const float p = __expf(sc[u][j] - mx[u]);
            sc[u][j] = p;
            lsum[u] += p;
        }
    }
#pragma unroll
    for (int u = 0; u < QG; u++) {
        float s = lsum[u];
#pragma unroll
        for (int o = 16; o > 0; o >>= 1) s += __shfl_xor_sync(0xffffffffu, s, o);
        if (lane == 0) red[u * 8 + wid] = s;
    }
    __syncthreads();
    float inv[QG];
#pragma unroll
    for (int u = 0; u < QG; u++) {
        float s = 0.f;
#pragma unroll
        for (int w = 0; w < 8; w++) s += red[u * 8 + w];
        inv[u] = 1.0f / s;
    }
    __syncthreads();

    // V pass: thread owns dim d, key-range group g4 (4 x 512 keys)
    const int d = t & 63, g4 = t >> 6;
    float acc[QG];
#pragma unroll
    for (int u = 0; u < QG; u++) acc[u] = 0.f;
    const int j0 = g4 * (LL / 4), j1 = j0 + (LL / 4);
    for (int j = j0; j < j1; j++) {
        const float v = vb[(size_t)j * DKK + d];
#pragma unroll
        for (int u = 0; u < QG; u++) acc[u] += sc[u][j] * v;
    }
#pragma unroll
    for (int u = 0; u < QG; u++) {
        red[t] = acc[u];
        __syncthreads();
        if (t < DKK) {
            const float o = (red[t] + red[t + 64] + red[t + 128] + red[t + 192]) * inv[u];
            g_att[(size_t)(bh * UU + grp * QG + u) * DKK + t] = o;
        }
        __syncthreads();
    }
}

__global__ __launch_bounds__(256) void cumsum_kernel()
{
    __shared__ float part[4][DKK];
    const int bh = blockIdx.x;
    const int b = bh >> 3, h = bh & 7;
    const int t = threadIdx.x;
    const int d = t & 63, c = t >> 6;
    const float* vb = g_v + (size_t)bh * LL * DKK;

    const int l0 = c * (LL / 4), l1 = l0 + (LL / 4);
    float s = 0.f;
    for (int l = l0; l < l1; l++) s += vb[(size_t)l * DKK + d];
    part[c][d] = s;
    __syncthreads();

    float off = 0.f;
    for (int cc = 0; cc < c; cc++) off += part[cc][d];

    float acc = off;
    float* cb = g_ctx + (size_t)b * LL * DD + h * DKK;
    for (int l = l0; l < l1; l++) {
        acc += vb[(size_t)l * DKK + d];
        cb[(size_t)l * DD + d] = acc;
    }
}

__global__ void scatter_kernel()
{
    const int i = blockIdx.x * blockDim.x + threadIdx.x;
    if (i >= BB * HH * UU * DKK) return;
    const int d = i & 63;
    const int r = i >> 6;
    const int bh = r / UU;
    const int b = bh >> 3, h = bh & 7;
    const int pos = g_top[r];
    g_ctx[((size_t)b * LL + pos) * DD + h * DKK + d] = g_att[i];
}

// ---------------------------------------------------------------------------
extern "C" void kernel_launch(void* const* d_in, const int* in_sizes, int n_in,
                              void* d_out, int out_size)
{
    const float* queries = (const float*)d_in[0];
    const float* keys    = (const float*)d_in[1];
    const float* values  = (const float*)d_in[2];
    const int*   index_sample = (const int*)d_in[3];
    const float* Wq = (const float*)d_in[4];
    const float* bq = (const float*)d_in[5];
    const float* Wk = (const float*)d_in[6];
    const float* bk = (const float*)d_in[7];
    const float* Wv = (const float*)d_in[8];
    const float* bv = (const float*)d_in[9];
    const float* Wo = (const float*)d_in[10];
    const float* bo = (const float*)d_in[11];
    float* out = (float*)d_out;

    cudaFuncSetAttribute(hgemm_qkv, cudaFuncAttributeMaxDynamicSharedMemorySize, GSMEM);
    cudaFuncSetAttribute(hgemm_out, cudaFuncAttributeMaxDynamicSharedMemorySize, GSMEM);

    transpose_split_kernel<<<dim3(16, 16, 4), dim3(32, 8)>>>(Wq, Wk, Wv, Wo);

    hgemm_qkv<<<dim3(DD / 128, MTOT / 128, 3), 256, GSMEM>>>(queries, keys, values, bq, bk, bv);

    probe_kernel<<<(BB * HH * LL * 32) / 256, 256>>>(index_sample);
    topk_kernel<<<BH, 256>>>();
    attn_kernel<<<BH * (UU / QG), 256>>>();
    cumsum_kernel<<<BH, 256>>>();
    scatter_kernel<<<(BB * HH * UU * DKK + 255) / 256, 256>>>();

    hgemm_out<<<dim3(DD / 128, MTOT / 128, 1), 256, GSMEM>>>(bo, out);
}

// round 7
// speedup vs baseline: 2.5567x; 1.2210x over previous
#include <cuda_runtime.h>
#include <cuda_bf16.h>
#include <math.h>
#include <stdint.h>

// Problem constants
#define BB 4
#define LL 2048
#define DD 512
#define HH 8
#define DKK 64
#define UU 24
#define BH (BB*HH)
#define MTOT (BB*LL)     // 8192 rows per GEMM

// ---------------- scratch (device globals; no allocation allowed) ----------
__device__ float g_q[BB*HH*LL*DKK];     // (B,H,L,DK)
__device__ float g_k[BB*HH*LL*DKK];
__device__ float g_v[BB*HH*LL*DKK];
__device__ float g_m[BB*HH*LL];
__device__ int   g_top[BB*HH*UU];
__device__ float g_att[BB*HH*UU*DKK];
__device__ float g_ctx[BB*LL*DD];       // (b, l, h*DK+dk)

// pre-split transposed weights W^T[n][k] in bf16 hi/lo (Wq,Wk,Wv,Wo)
__device__ __nv_bfloat16 g_wh[4][DD*DD];
__device__ __nv_bfloat16 g_wl[4][DD*DD];

// cumsum scratch
__device__ float g_segsum[BH][16][4][DKK];
__device__ float g_chpre[BH][16][DKK];

// =========================== helpers =======================================
__device__ __forceinline__ uint32_t smem_u32(const void* p) {
    uint32_t a;
    asm("{ .reg .u64 t; cvta.to.shared.u64 t, %1; cvt.u32.u64 %0, t; }"
        : "=r"(a) : "l"(p));
    return a;
}
__device__ __forceinline__ void cpasync16(uint32_t saddr, const void* gptr) {
    asm volatile("cp.async.cg.shared.global [%0], [%1], 16;"
                 :: "r"(saddr), "l"(__cvta_generic_to_global(gptr)) : "memory");
}
__device__ __forceinline__ void cp_commit() {
    asm volatile("cp.async.commit_group;" ::: "memory");
}
template<int N>
__device__ __forceinline__ void cp_wait() {
    asm volatile("cp.async.wait_group %0;" :: "n"(N) : "memory");
}
__device__ __forceinline__ void mma_bf16(float& c0, float& c1, float& c2, float& c3,
                                         uint32_t a0, uint32_t a1, uint32_t a2, uint32_t a3,
                                         uint32_t b0, uint32_t b1) {
    asm volatile("mma.sync.aligned.m16n8k16.row.col.f32.bf16.bf16.f32 "
                 "{%0,%1,%2,%3}, {%4,%5,%6,%7}, {%8,%9}, {%0,%1,%2,%3};"
                 : "+f"(c0), "+f"(c1), "+f"(c2), "+f"(c3)
                 : "r"(a0), "r"(a1), "r"(a2), "r"(a3), "r"(b0), "r"(b1));
}
__device__ __forceinline__ void ldsm4(uint32_t& r0, uint32_t& r1, uint32_t& r2, uint32_t& r3,
                                      uint32_t addr) {
    asm volatile("ldmatrix.sync.aligned.m8n8.x4.shared.b16 {%0,%1,%2,%3}, [%4];"
                 : "=r"(r0), "=r"(r1), "=r"(r2), "=r"(r3) : "r"(addr));
}
__device__ __forceinline__ void split2(float x, __nv_bfloat16& h, __nv_bfloat16& l) {
    h = __float2bfloat16_rn(x);
    l = __float2bfloat16_rn(x - __bfloat162float(h));
}
__device__ __forceinline__ uint32_t pack2(__nv_bfloat16 a, __nv_bfloat16 b) {
    return (uint32_t)__bfloat16_as_ushort(a) | ((uint32_t)__bfloat16_as_ushort(b) << 16);
}

// W[k][n] -> W^T[n][k] bf16 hi/lo, tiled transpose. grid (16,16,4), block (32,8)
__global__ __launch_bounds__(256) void transpose_split_kernel(const float* __restrict__ Wq,
                                                              const float* __restrict__ Wk,
                                                              const float* __restrict__ Wv,
                                                              const float* __restrict__ Wo)
{
    __shared__ float tile[32][33];
    const int z = blockIdx.z;
    const float* W = (z == 0) ? Wq : (z == 1) ? Wk : (z == 2) ? Wv : Wo;
    const int k0 = blockIdx.y * 32, n0 = blockIdx.x * 32;
#pragma unroll
    for (int r = 0; r < 32; r += 8)
        tile[threadIdx.y + r][threadIdx.x] = W[(size_t)(k0 + threadIdx.y + r) * DD + n0 + threadIdx.x];
    __syncthreads();
#pragma unroll
    for (int r = 0; r < 32; r += 8) {
        const int n = n0 + threadIdx.y + r, k = k0 + threadIdx.x;
        __nv_bfloat16 h, l;
        split2(tile[threadIdx.x][threadIdx.y + r], h, l);
        g_wh[z][(size_t)n * DD + k] = h;
        g_wl[z][(size_t)n * DD + k] = l;
    }
}

// =========================== HMMA GEMM (fused split, ldmatrix) =============
#define STG 40                        // smem row stride, bf16 elems
#define ARR_E (128*STG)
#define ARR_B (ARR_E*2)
#define AF_STRIDE 36
#define AF_B (128*AF_STRIDE*4)
#define OFF_AF 0
#define OFF_AH (AF_B)
#define OFF_AL (OFF_AH + ARR_B)
#define OFF_BH (OFF_AL + ARR_B)
#define OFF_BL (OFF_BH + ARR_B)
#define STAGE_B (OFF_BL + ARR_B)      // 59392
#define GSMEM (2*STAGE_B)             // 118784

__device__ __forceinline__ void gemm_load_chunk(const float* __restrict__ A,
                                                const __nv_bfloat16* __restrict__ Bh,
                                                const __nv_bfloat16* __restrict__ Bl,
                                                uint32_t sbase, int stage,
                                                int m0, int n0, int k0, int tid)
{
    const uint32_t s = sbase + stage * STAGE_B;
#pragma unroll
    for (int rep = 0; rep < 4; rep++) {
        const int c = tid + rep * 256;
        const int row = c >> 3, kp = (c & 7) * 4;
        cpasync16(s + OFF_AF + (uint32_t)(row * AF_STRIDE + kp) * 4,
                  A + (size_t)(m0 + row) * DD + k0 + kp);
    }
#pragma unroll
    for (int rep = 0; rep < 2; rep++) {
        const int c = tid + rep * 256;
        const int row = c >> 2, kp = (c & 3) * 8;
        cpasync16(s + OFF_BH + (uint32_t)(row * STG + kp) * 2,
                  Bh + (size_t)(n0 + row) * DD + k0 + kp);
    }
#pragma unroll
    for (int rep = 0; rep < 2; rep++) {
        const int c = tid + rep * 256;
        const int row = c >> 2, kp = (c & 3) * 8;
        cpasync16(s + OFF_BL + (uint32_t)(row * STG + kp) * 2,
                  Bl + (size_t)(n0 + row) * DD + k0 + kp);
    }
    cp_commit();
}

template<int SCATTER>
__device__ __forceinline__ void gemm_core(const float* __restrict__ A,
                                          const __nv_bfloat16* __restrict__ Bh,
                                          const __nv_bfloat16* __restrict__ Bl,
                                          const float* __restrict__ bias,
                                          float* __restrict__ dst, char* smraw)
{
    const int tid = threadIdx.x;
    const int m0 = blockIdx.y * 128, n0 = blockIdx.x * 128;
    const uint32_t sbase = smem_u32(smraw);

    const int wid = tid >> 5, lane = tid & 31;
    const int wm = (wid >> 2) * 64;       // 0 or 64
    const int wn = (wid & 3) * 32;        // 0,32,64,96
    const int g  = lane >> 2;             // 0..7
    const int q2 = (lane & 3) * 2;        // 0,2,4,6

    // ldmatrix per-lane address components (elements)
    const int aRow = wm + (lane & 7) + ((lane >> 3) & 1) * 8;   // + i*16
    const int aColE = (lane >> 4) * 8;                          // + ks
    const int bRow = wn + (lane & 7) + ((lane >> 4) & 1) * 8;   // + jp*16
    const int bColE = ((lane >> 3) & 1) * 8;                    // + ks

    float acc[4][4][4];
#pragma unroll
    for (int i = 0; i < 4; i++)
#pragma unroll
        for (int j = 0; j < 4; j++)
#pragma unroll
            for (int r = 0; r < 4; r++) acc[i][j][r] = 0.f;

    gemm_load_chunk(A, Bh, Bl, sbase, 0, m0, n0, 0, tid);

    for (int c = 0; c < 16; c++) {
        const int st = c & 1;
        if (c < 15) {
            gemm_load_chunk(A, Bh, Bl, sbase, st ^ 1, m0, n0, (c + 1) * 32, tid);
            cp_wait<1>();
        } else {
            cp_wait<0>();
        }
        __syncthreads();

        // in-smem split: Af32(st) -> Ah(st), Al(st)
        {
            char* sp = smraw + st * STAGE_B;
            const float* af = (const float*)(sp + OFF_AF);
            __nv_bfloat16* ah = (__nv_bfloat16*)(sp + OFF_AH);
            __nv_bfloat16* al = (__nv_bfloat16*)(sp + OFF_AL);
            const int row = tid >> 1, half = (tid & 1) * 16;
#pragma unroll
            for (int qq = 0; qq < 4; qq++) {
                float4 v = *(const float4*)(af + row * AF_STRIDE + half + qq * 4);
                __nv_bfloat16 h0, h1, h2, h3, l0, l1, l2, l3;
                split2(v.x, h0, l0); split2(v.y, h1, l1);
                split2(v.z, h2, l2); split2(v.w, h3, l3);
                uint2 uh = { pack2(h0, h1), pack2(h2, h3) };
                uint2 ul = { pack2(l0, l1), pack2(l2, l3) };
                *(uint2*)(ah + row * STG + half + qq * 4) = uh;
                *(uint2*)(al + row * STG + half + qq * 4) = ul;
            }
        }
        __syncthreads();

        const uint32_t stb = sbase + st * STAGE_B;
        const uint32_t aH = stb + OFF_AH + (uint32_t)(aRow * STG + aColE) * 2;
        const uint32_t aL = stb + OFF_AL + (uint32_t)(aRow * STG + aColE) * 2;
        const uint32_t bH = stb + OFF_BH + (uint32_t)(bRow * STG + bColE) * 2;
        const uint32_t bL = stb + OFF_BL + (uint32_t)(bRow * STG + bColE) * 2;

#pragma unroll
        for (int ks = 0; ks < 32; ks += 16) {
            uint32_t ah4[4][4], al4[4][4], bh4[2][4], bl4[2][4];
#pragma unroll
            for (int i = 0; i < 4; i++)
                ldsm4(ah4[i][0], ah4[i][1], ah4[i][2], ah4[i][3],
                      aH + (uint32_t)(i * 16 * STG + ks) * 2);
#pragma unroll
            for (int jp = 0; jp < 2; jp++)
                ldsm4(bh4[jp][0], bh4[jp][1], bh4[jp][2], bh4[jp][3],
                      bH + (uint32_t)(jp * 16 * STG + ks) * 2);
#pragma unroll
            for (int jp = 0; jp < 2; jp++)
                ldsm4(bl4[jp][0], bl4[jp][1], bl4[jp][2], bl4[jp][3],
                      bL + (uint32_t)(jp * 16 * STG + ks) * 2);
#pragma unroll
            for (int i = 0; i < 4; i++)
                ldsm4(al4[i][0], al4[i][1], al4[i][2], al4[i][3],
                      aL + (uint32_t)(i * 16 * STG + ks) * 2);

#pragma unroll
            for (int i = 0; i < 4; i++)
#pragma unroll
                for (int j = 0; j < 4; j++) {
                    const int jp = j >> 1, jo = (j & 1) * 2;
                    mma_bf16(acc[i][j][0], acc[i][j][1], acc[i][j][2], acc[i][j][3],
                             ah4[i][0], ah4[i][1], ah4[i][2], ah4[i][3],
                             bh4[jp][jo], bh4[jp][jo + 1]);
                }
#pragma unroll
            for (int i = 0; i < 4; i++)
#pragma unroll
                for (int j = 0; j < 4; j++) {
                    const int jp = j >> 1, jo = (j & 1) * 2;
                    mma_bf16(acc[i][j][0], acc[i][j][1], acc[i][j][2], acc[i][j][3],
                             ah4[i][0], ah4[i][1], ah4[i][2], ah4[i][3],
                             bl4[jp][jo], bl4[jp][jo + 1]);
                }
#pragma unroll
            for (int i = 0; i < 4; i++)
#pragma unroll
                for (int j = 0; j < 4; j++) {
                    const int jp = j >> 1, jo = (j & 1) * 2;
                    mma_bf16(acc[i][j][0], acc[i][j][1], acc[i][j][2], acc[i][j][3],
                             al4[i][0], al4[i][1], al4[i][2], al4[i][3],
                             bh4[jp][jo], bh4[jp][jo + 1]);
                }
        }
        __syncthreads();
    }

    // epilogue
#pragma unroll
    for (int i = 0; i < 4; i++) {
#pragma unroll
        for (int j = 0; j < 4; j++) {
            const int gm0 = m0 + wm + i * 16 + g;
            const int gn  = n0 + wn + j * 8 + q2;
            const float b0 = bias[gn], b1 = bias[gn + 1];
            const float v0 = acc[i][j][0] + b0, v1 = acc[i][j][1] + b1;
            const float v2 = acc[i][j][2] + b0, v3 = acc[i][j][3] + b1;
            if (SCATTER == 0) {
                float* p0 = dst + (size_t)gm0 * DD + gn;
                p0[0] = v0; p0[1] = v1;
                float* p1 = dst + (size_t)(gm0 + 8) * DD + gn;
                p1[0] = v2; p1[1] = v3;
            } else {
                const int h = gn >> 6, dk = gn & 63;
                {
                    const int b = gm0 >> 11, l = gm0 & 2047;
                    float* p = dst + (((size_t)(b * HH + h)) * LL + l) * DKK + dk;
                    p[0] = v0; p[1] = v1;
                }
                {
                    const int gm1 = gm0 + 8;
                    const int b = gm1 >> 11, l = gm1 & 2047;
                    float* p = dst + (((size_t)(b * HH + h)) * LL + l) * DKK + dk;
                    p[0] = v2; p[1] = v3;
                }
            }
        }
    }
}

__global__ __launch_bounds__(256, 1) void hgemm_qkv(const float* __restrict__ q,
                                                    const float* __restrict__ k,
                                                    const float* __restrict__ v,
                                                    const float* __restrict__ bq,
                                                    const float* __restrict__ bk,
                                                    const float* __restrict__ bv)
{
    extern __shared__ char smraw[];
    const int z = blockIdx.z;
    const float* A = (z == 0) ? q : (z == 1) ? k : v;
    const float* bias = (z == 0) ? bq : (z == 1) ? bk : bv;
    float* dst = (z == 0) ? g_q : (z == 1) ? g_k : g_v;
    gemm_core<1>(A, g_wh[z], g_wl[z], bias, dst, smraw);
}

__global__ __launch_bounds__(256, 1) void hgemm_out(const float* __restrict__ bo,
                                                    float* __restrict__ outp)
{
    extern __shared__ char smraw[];
    gemm_core<0>((const float*)g_ctx, g_wh[3], g_wl[3], bo, outp, smraw);
}

// =========================== non-GEMM kernels ==============================
__global__ __launch_bounds__(256) void probe_kernel(const int* __restrict__ idx)
{
    const int w = (blockIdx.x * blockDim.x + threadIdx.x) >> 5;
    const int lane = threadIdx.x & 31;
    if (w >= BB * HH * LL) return;
    const int l = w & (LL - 1);
    const int bh = w >> 11;

    const float* qrow = g_q + (size_t)(bh * LL + l) * DKK;
    const float2 qv = *(const float2*)(qrow + lane * 2);
    const float* kbase = g_k + (size_t)bh * LL * DKK;
    const int* ip = idx + l * UU;
    const int myidx = (lane < UU) ? ip[lane] : 0;

    float mx = -INFINITY, sm = 0.f;
#pragma unroll 4
    for (int s = 0; s < UU; s++) {
        const int j = __shfl_sync(0xffffffffu, myidx, s);
        const float2 kk = *(const float2*)(kbase + (size_t)j * DKK + lane * 2);
        float p = qv.x * kk.x + qv.y * kk.y;
#pragma unroll
        for (int o = 16; o > 0; o >>= 1) p += __shfl_xor_sync(0xffffffffu, p, o);
        mx = fmaxf(mx, p);
        sm += p;
    }
    if (lane == 0) g_m[w] = mx - sm * (1.0f / LL);
}

// Top-24: values register-resident, shuffle reduce, 2 barriers/iter
__global__ __launch_bounds__(256) void topk_kernel()
{
    __shared__ float swv[8];
    __shared__ int   swi[8];
    __shared__ int   swin;
    const int bh = blockIdx.x;
    const int t = threadIdx.x;
    const int wid = t >> 5, lane = t & 31;

    float v[8];
#pragma unroll
    for (int j = 0; j < 8; j++) v[j] = g_m[(size_t)bh * LL + j * 256 + t];

    for (int iter = 0; iter < UU; iter++) {
        float bv = v[0]; int bj = 0;
#pragma unroll
        for (int j = 1; j < 8; j++) if (v[j] > bv) { bv = v[j]; bj = j; }
        int bi = bj * 256 + t;
#pragma unroll
        for (int o = 16; o > 0; o >>= 1) {
            const float ov = __shfl_xor_sync(0xffffffffu, bv, o);
            const int   oi = __shfl_xor_sync(0xffffffffu, bi, o);
            if (ov > bv || (ov == bv && oi < bi)) { bv = ov; bi = oi; }
        }
        if (lane == 0) { swv[wid] = bv; swi[wid] = bi; }
        __syncthreads();
        if (t == 0) {
            float mv = swv[0]; int mi = swi[0];
#pragma unroll
            for (int w = 1; w < 8; w++)
                if (swv[w] > mv || (swv[w] == mv && swi[w] < mi)) { mv = swv[w]; mi = swi[w]; }
            g_top[bh * UU + iter] = mi;
            swin = mi;
        }
        __syncthreads();
        const int win = swin;
        if ((win & 255) == t) v[win >> 8] = -INFINITY;
    }
}

// Batched sparse attention: one block per (bh, group of 4 top queries)
#define QG 4
__global__ __launch_bounds__(256) void attn_kernel()
{
    __shared__ float qs[QG][DKK];
    __shared__ float sc[QG][LL];
    __shared__ float red[256];
    __shared__ int   pos_s[QG];

    const int bh = blockIdx.x / (UU / QG);
    const int grp = blockIdx.x % (UU / QG);
    const int t = threadIdx.x;
    const int wid = t >> 5, lane = t & 31;

    const float* kb = g_k + (size_t)bh * LL * DKK;
    const float* vb = g_v + (size_t)bh * LL * DKK;

    {
        const int u = t >> 6, d = t & 63;
        const int p = g_top[bh * UU + grp * QG + u];
        if (d == 0) pos_s[u] = p;
        qs[u][d] = g_q[((size_t)bh * LL + p) * DKK + d];
    }
    __syncthreads();

    const float scale = rsqrtf((float)DD);

    float lmax[QG];
#pragma unroll
    for (int u = 0; u < QG; u++) lmax[u] = -INFINITY;

    for (int j = t; j < LL; j += 256) {
        const float* kr = kb + (size_t)j * DKK;
        float dot[QG];
#pragma unroll
        for (int u = 0; u < QG; u++) dot[u] = 0.f;
#pragma unroll
        for (int d4 = 0; d4 < 16; d4++) {
            float4 kk = *(const float4*)(kr + d4 * 4);
#pragma unroll
            for (int u = 0; u < QG; u++) {
                dot[u] += qs[u][d4 * 4] * kk.x + qs[u][d4 * 4 + 1] * kk.y +
                          qs[u][d4 * 4 + 2] * kk.z + qs[u][d4 * 4 + 3] * kk.w;
            }
        }
#pragma unroll
        for (int u = 0; u < QG; u++) {
            const float s = (j > pos_s[u]) ? -INFINITY : dot[u] * scale;
            sc[u][j] = s;
            lmax[u] = fmaxf(lmax[u], s);
        }
    }
#pragma unroll
    for (int u = 0; u < QG; u++) {
        float m = lmax[u];
#pragma unroll
        for (int o = 16; o > 0; o >>= 1) m = fmaxf(m, __shfl_xor_sync(0xffffffffu, m, o));
        if (lane == 0) red[u * 8 + wid] = m;
    }
    __syncthreads();
    float mx[QG];
#pragma unroll
    for (int u = 0; u < QG; u++) {
        float m = -INFINITY;
#pragma unroll
        for (int w = 0; w < 8; w++) m = fmaxf(m, red[u * 8 + w]);
        mx[u] = m;
    }
    __syncthreads();

    float lsum[QG];
#pragma unroll
    for (int u = 0; u < QG; u++) lsum[u] = 0.f;
    for (int j = t; j < LL; j += 256) {
#pragma unroll
        for (int u = 0; u < QG; u++) {
            const float p = __expf(sc[u][j] - mx[u]);
            sc[u][j] = p;
            lsum[u] += p;
        }
    }
#pragma unroll
    for (int u = 0; u < QG; u++) {
        float s = lsum[u];
#pragma unroll
        for (int o = 16; o > 0; o >>= 1) s += __shfl_xor_sync(0xffffffffu, s, o);
        if (lane == 0) red[u * 8 + wid] = s;
    }
    __syncthreads();
    float inv[QG];
#pragma unroll
    for (int u = 0; u < QG; u++) {
        float s = 0.f;
#pragma unroll
        for (int w = 0; w < 8; w++) s += red[u * 8 + w];
        inv[u] = 1.0f / s;
    }
    __syncthreads();

    const int d = t & 63, g4 = t >> 6;
    float acc[QG];
#pragma unroll
    for (int u = 0; u < QG; u++) acc[u] = 0.f;
    const int j0 = g4 * (LL / 4), j1 = j0 + (LL / 4);
    for (int j = j0; j < j1; j++) {
        const float v = vb[(size_t)j * DKK + d];
#pragma unroll
        for (int u = 0; u < QG; u++) acc[u] += sc[u][j] * v;
    }
#pragma unroll
    for (int u = 0; u < QG; u++) {
        red[t] = acc[u];
        __syncthreads();
        if (t < DKK) {
            const float o = (red[t] + red[t + 64] + red[t + 128] + red[t + 192]) * inv[u];
            g_att[(size_t)(bh * UU + grp * QG + u) * DKK + t] = o;
        }
        __syncthreads();
    }
}

// ---- cumsum, 3-phase ------------------------------------------------------
__global__ __launch_bounds__(256) void cumsum_p1()
{
    const int bh = blockIdx.x, ch = blockIdx.y;
    const int t = threadIdx.x;
    const int d = t & 63, seg = t >> 6;
    const float* vb = g_v + (size_t)bh * LL * DKK;
    const int l0 = ch * 128 + seg * 32;
    float s = 0.f;
#pragma unroll 4
    for (int l = l0; l < l0 + 32; l++) s += vb[(size_t)l * DKK + d];
    g_segsum[bh][ch][seg][d] = s;
}
__global__ __launch_bounds__(64) void cumsum_p2()
{
    const int bh = blockIdx.x, d = threadIdx.x;
    float run = 0.f;
#pragma unroll
    for (int ch = 0; ch < 16; ch++) {
        g_chpre[bh][ch][d] = run;
        run += g_segsum[bh][ch][0][d] + g_segsum[bh][ch][1][d] +
               g_segsum[bh][ch][2][d] + g_segsum[bh][ch][3][d];
    }
}
__global__ __launch_bounds__(256) void cumsum_p3()
{
    const int bh = blockIdx.x, ch = blockIdx.y;
    const int b = bh >> 3, h = bh & 7;
    const int t = threadIdx.x;
    const int d = t & 63, seg = t >> 6;
    const float* vb = g_v + (size_t)bh * LL * DKK;

    float off = g_chpre[bh][ch][d];
    for (int s = 0; s < seg; s++) off += g_segsum[bh][ch][s][d];

    const int l0 = ch * 128 + seg * 32;
    float acc = off;
    float* cb = g_ctx + (size_t)b * LL * DD + h * DKK;
#pragma unroll 4
    for (int l = l0; l < l0 + 32; l++) {
        acc += vb[(size_t)l * DKK + d];
        cb[(size_t)l * DD + d] = acc;
    }
}

__global__ void scatter_kernel()
{
    const int i = blockIdx.x * blockDim.x + threadIdx.x;
    if (i >= BB * HH * UU * DKK) return;
    const int d = i & 63;
    const int r = i >> 6;
    const int bh = r / UU;
    const int b = bh >> 3, h = bh & 7;
    const int pos = g_top[r];
    g_ctx[((size_t)b * LL + pos) * DD + h * DKK + d] = g_att[i];
}

// ---------------------------------------------------------------------------
extern "C" void kernel_launch(void* const* d_in, const int* in_sizes, int n_in,
                              void* d_out, int out_size)
{
    const float* queries = (const float*)d_in[0];
    const float* keys    = (const float*)d_in[1];
    const float* values  = (const float*)d_in[2];
    const int*   index_sample = (const int*)d_in[3];
    const float* Wq = (const float*)d_in[4];
    const float* bq = (const float*)d_in[5];
    const float* Wk = (const float*)d_in[6];
    const float* bk = (const float*)d_in[7];
    const float* Wv = (const float*)d_in[8];
    const float* bv = (const float*)d_in[9];
    const float* Wo = (const float*)d_in[10];
    const float* bo = (const float*)d_in[11];
    float* out = (float*)d_out;

    cudaFuncSetAttribute(hgemm_qkv, cudaFuncAttributeMaxDynamicSharedMemorySize, GSMEM);
    cudaFuncSetAttribute(hgemm_out, cudaFuncAttributeMaxDynamicSharedMemorySize, GSMEM);

    transpose_split_kernel<<<dim3(16, 16, 4), dim3(32, 8)>>>(Wq, Wk, Wv, Wo);

    hgemm_qkv<<<dim3(DD / 128, MTOT / 128, 3), 256, GSMEM>>>(queries, keys, values, bq, bk, bv);

    probe_kernel<<<(BB * HH * LL * 32) / 256, 256>>>(index_sample);
    topk_kernel<<<BH, 256>>>();
    attn_kernel<<<BH * (UU / QG), 256>>>();
    cumsum_p1<<<dim3(BH, 16), 256>>>();
    cumsum_p2<<<BH, 64>>>();
    cumsum_p3<<<dim3(BH, 16), 256>>>();
    scatter_kernel<<<(BB * HH * UU * DKK + 255) / 256, 256>>>();

    hgemm_out<<<dim3(DD / 128, MTOT / 128, 1), 256, GSMEM>>>(bo, out);
}